// round 1
// baseline (speedup 1.0000x reference)
#include <cuda_runtime.h>
#include <cuda_bf16.h>

#define N_IN  5023
#define N_OUT 5023
#define HD    256
#define BB    64
#define MP    5120          // padded M/N/K dim for both GEMMs
#define NV    192           // B*3 columns of V

// -------- scratch (device globals; no allocation at runtime) --------
__device__ float g_scoreT[(size_t)MP * MP];   // [o][i], lda = MP
__device__ float g_Qp[HD * MP];               // [h][o]  padded query_w
__device__ float g_Kp[MP * HD];               // [i][h]  padded key_w
__device__ float g_V[(size_t)MP * NV];        // [i][n]  (x @ value_w^T) / l1[i], padded rows
__device__ float g_l1p[40 * MP];              // partial L1 sums
__device__ float g_l1[MP];                    // final L1 sums

// -------------------- padding / prep kernels --------------------
__global__ void pad_q(const float* __restrict__ qw) {
    int idx = blockIdx.x * blockDim.x + threadIdx.x;
    if (idx >= HD * MP) return;
    int h = idx / MP, o = idx % MP;
    g_Qp[idx] = (o < N_OUT) ? qw[h * N_OUT + o] : 0.f;
}

__global__ void pad_k(const float* __restrict__ kw) {
    int idx = blockIdx.x * blockDim.x + threadIdx.x;
    if (idx >= MP * HD) return;
    int i = idx / HD;
    g_Kp[idx] = (i < N_IN) ? kw[i * HD + (idx % HD)] : 0.f;
}

// V[i, b*3+d] = sum_e x[b,i,e] * vw[d,e]   (unscaled; scaled later by 1/l1[i])
__global__ void vmat(const float* __restrict__ x, const float* __restrict__ vw) {
    int idx = blockIdx.x * blockDim.x + threadIdx.x;
    if (idx >= MP * NV) return;
    int i = idx / NV, n = idx % NV;
    float val = 0.f;
    if (i < N_IN) {
        int b = n / 3, d = n % 3;
        const float* xp = x + ((size_t)b * N_IN + i) * 3;
        val = xp[0] * vw[d * 3 + 0] + xp[1] * vw[d * 3 + 1] + xp[2] * vw[d * 3 + 2];
    }
    g_V[idx] = val;
}

// -------------------- GEMM1: scoreT[o,i] = (1/16) * sum_h Qp[h][o] * Kp[i][h] ----
// 128x128 tile, BK=8, 256 threads, 8x8 per thread.
__global__ __launch_bounds__(256) void gemm1() {
    __shared__ float As[8][128];   // [k][o]
    __shared__ float Bs[8][128];   // [k][i]
    const int tid   = threadIdx.x;
    const int obase = blockIdx.y * 128;
    const int ibase = blockIdx.x * 128;

    const int a_h  = tid >> 5;         // 0..7
    const int a_o  = (tid & 31) * 4;   // 0..124
    const int b_i  = tid >> 1;         // 0..127
    const int b_h4 = (tid & 1) * 4;    // 0 or 4
    const int trow = (tid >> 4) * 8;   // o in tile
    const int tcol = (tid & 15) * 8;   // i in tile

    float acc[8][8] = {};

    for (int k0 = 0; k0 < HD; k0 += 8) {
        float4 av = *(const float4*)&g_Qp[(size_t)(k0 + a_h) * MP + obase + a_o];
        *(float4*)&As[a_h][a_o] = av;
        float4 bv = *(const float4*)&g_Kp[(size_t)(ibase + b_i) * HD + k0 + b_h4];
        Bs[b_h4 + 0][b_i] = bv.x;
        Bs[b_h4 + 1][b_i] = bv.y;
        Bs[b_h4 + 2][b_i] = bv.z;
        Bs[b_h4 + 3][b_i] = bv.w;
        __syncthreads();
        #pragma unroll
        for (int kk = 0; kk < 8; kk++) {
            float ra[8], rb[8];
            #pragma unroll
            for (int u = 0; u < 8; u++) ra[u] = As[kk][trow + u];
            #pragma unroll
            for (int u = 0; u < 8; u++) rb[u] = Bs[kk][tcol + u];
            #pragma unroll
            for (int y = 0; y < 8; y++)
                #pragma unroll
                for (int xq = 0; xq < 8; xq++)
                    acc[y][xq] += ra[y] * rb[xq];
        }
        __syncthreads();
    }

    #pragma unroll
    for (int y = 0; y < 8; y++) {
        size_t row = (size_t)(obase + trow + y) * MP + ibase + tcol;
        float4 v0 = make_float4(acc[y][0] * 0.0625f, acc[y][1] * 0.0625f,
                                acc[y][2] * 0.0625f, acc[y][3] * 0.0625f);
        float4 v1 = make_float4(acc[y][4] * 0.0625f, acc[y][5] * 0.0625f,
                                acc[y][6] * 0.0625f, acc[y][7] * 0.0625f);
        *(float4*)&g_scoreT[row]     = v0;
        *(float4*)&g_scoreT[row + 4] = v1;
    }
}

// -------------------- L1 column sums (two-stage, deterministic) --------------------
__global__ void l1_partial() {
    int i = blockIdx.x * blockDim.x + threadIdx.x;   // column
    if (i >= MP) return;
    int o0 = blockIdx.y * 128;
    float s = 0.f;
    for (int o = o0; o < o0 + 128; o++)
        s += fabsf(g_scoreT[(size_t)o * MP + i]);
    g_l1p[blockIdx.y * MP + i] = s;
}

__global__ void l1_final() {
    int i = blockIdx.x * blockDim.x + threadIdx.x;
    if (i >= MP) return;
    float s = 0.f;
    #pragma unroll
    for (int y = 0; y < 40; y++) s += g_l1p[y * MP + i];
    g_l1[i] = s;
}

// Scale V rows by 1/max(l1, eps)
__global__ void scale_v() {
    int idx = blockIdx.x * blockDim.x + threadIdx.x;
    if (idx >= MP * NV) return;
    int i = idx / NV;
    if (i >= N_IN) return;   // padded rows already zero
    float r = 1.f / fmaxf(g_l1[i], 1e-12f);
    g_V[idx] *= r;
}

// -------------------- GEMM2: out[o,n] = sum_i scoreT[o,i] * Vs[i,n] --------------------
// 64x64 tile, BK=16, 256 threads, 4x4 per thread. K=MP (padding is zero).
__global__ __launch_bounds__(256) void gemm2(float* __restrict__ out) {
    __shared__ float As[16][64];   // [k][o]
    __shared__ float Bs[16][64];   // [k][n]
    const int tid   = threadIdx.x;
    const int obase = blockIdx.y * 64;
    const int nbase = blockIdx.x * 64;

    const int a_o  = tid >> 2;         // 0..63
    const int a_k4 = (tid & 3) * 4;    // 0,4,8,12
    const int b_k  = tid >> 4;         // 0..15
    const int b_n4 = (tid & 15) * 4;   // 0..60
    const int trow = (tid >> 4) * 4;   // o in tile
    const int tcol = (tid & 15) * 4;   // n in tile

    float acc[4][4] = {};

    for (int k0 = 0; k0 < MP; k0 += 16) {
        float4 av = *(const float4*)&g_scoreT[(size_t)(obase + a_o) * MP + k0 + a_k4];
        As[a_k4 + 0][a_o] = av.x;
        As[a_k4 + 1][a_o] = av.y;
        As[a_k4 + 2][a_o] = av.z;
        As[a_k4 + 3][a_o] = av.w;
        float4 bv = *(const float4*)&g_V[(size_t)(k0 + b_k) * NV + nbase + b_n4];
        *(float4*)&Bs[b_k][b_n4] = bv;
        __syncthreads();
        #pragma unroll
        for (int kk = 0; kk < 16; kk++) {
            float ra[4], rb[4];
            #pragma unroll
            for (int u = 0; u < 4; u++) ra[u] = As[kk][trow + u];
            #pragma unroll
            for (int u = 0; u < 4; u++) rb[u] = Bs[kk][tcol + u];
            #pragma unroll
            for (int y = 0; y < 4; y++)
                #pragma unroll
                for (int xq = 0; xq < 4; xq++)
                    acc[y][xq] += ra[y] * rb[xq];
        }
        __syncthreads();
    }

    #pragma unroll
    for (int y = 0; y < 4; y++) {
        int o = obase + trow + y;
        if (o >= N_OUT) continue;
        #pragma unroll
        for (int xq = 0; xq < 4; xq++) {
            int n = nbase + tcol + xq;     // n < 192 always
            int b = n / 3, d = n % 3;
            out[((size_t)b * N_OUT + o) * 3 + d] = acc[y][xq];
        }
    }
}

// -------------------- launch --------------------
extern "C" void kernel_launch(void* const* d_in, const int* in_sizes, int n_in,
                              void* d_out, int out_size) {
    const float* x  = (const float*)d_in[0];   // [64, 5023, 3]
    const float* kw = (const float*)d_in[1];   // [5023, 256]
    const float* qw = (const float*)d_in[2];   // [256, 5023]
    const float* vw = (const float*)d_in[3];   // [3, 3]
    float* out = (float*)d_out;                // [64, 5023, 3]

    (void)in_sizes; (void)n_in; (void)out_size;

    pad_q<<<(HD * MP + 255) / 256, 256>>>(qw);
    pad_k<<<(MP * HD + 255) / 256, 256>>>(kw);
    vmat <<<(MP * NV + 255) / 256, 256>>>(x, vw);

    gemm1<<<dim3(MP / 128, MP / 128), 256>>>();

    l1_partial<<<dim3(MP / 256, 40), 256>>>();
    l1_final  <<<MP / 256, 256>>>();
    scale_v   <<<(MP * NV + 255) / 256, 256>>>();

    gemm2<<<dim3(NV / 64, MP / 64), 256>>>(out);
}

// round 2
// speedup vs baseline: 1.6212x; 1.6212x over previous
#include <cuda_runtime.h>
#include <cuda_bf16.h>
#include <cstdint>

#define N_IN  5023
#define N_OUT 5023
#define HD    256
#define MP    5120
#define NV    192
#define SKEW  40   // smem row stride in bf16 elems: 80B, 16B-aligned, conflict-free mod 128B

// -------- scratch (device globals) --------
__device__ __nv_bfloat16 g_Qh[(size_t)MP * HD], g_Ql[(size_t)MP * HD]; // A1 [o][h]
__device__ __nv_bfloat16 g_Kh[(size_t)MP * HD], g_Kl[(size_t)MP * HD]; // B1 [i][h]
__device__ __nv_bfloat16 g_Sh[(size_t)MP * MP], g_Sl[(size_t)MP * MP]; // score [o][i]
__device__ __nv_bfloat16 g_Vh[(size_t)NV * MP], g_Vl[(size_t)NV * MP]; // Vt [n][i]
__device__ float g_l1p[40 * MP];
__device__ float g_rl1[MP];

// -------- helpers --------
__device__ __forceinline__ uint32_t s2u(const void* p) {
    return (uint32_t)__cvta_generic_to_shared(p);
}
__device__ __forceinline__ void ldsm4(uint32_t* r, uint32_t a) {
    asm volatile("ldmatrix.sync.aligned.m8n8.x4.shared.b16 {%0,%1,%2,%3}, [%4];"
                 : "=r"(r[0]), "=r"(r[1]), "=r"(r[2]), "=r"(r[3]) : "r"(a));
}
__device__ __forceinline__ void mma16816(float* d, const uint32_t* a, const uint32_t* b) {
    asm volatile("mma.sync.aligned.m16n8k16.row.col.f32.bf16.bf16.f32 "
                 "{%0,%1,%2,%3},{%4,%5,%6,%7},{%8,%9},{%0,%1,%2,%3};"
                 : "+f"(d[0]), "+f"(d[1]), "+f"(d[2]), "+f"(d[3])
                 : "r"(a[0]), "r"(a[1]), "r"(a[2]), "r"(a[3]), "r"(b[0]), "r"(b[1]));
}
__device__ __forceinline__ void bsplit(float v, __nv_bfloat16& h, __nv_bfloat16& l) {
    h = __float2bfloat16(v);
    l = __float2bfloat16(v - __bfloat162float(h));
}

// -------- prep: split Q (transposed) and K into bf16 hi/lo --------
__global__ void qsplit(const float* __restrict__ qw) {
    int idx = blockIdx.x * 256 + threadIdx.x;
    if (idx >= MP * HD) return;
    int o = idx / HD, h = idx % HD;
    float v = (o < N_OUT) ? qw[(size_t)h * N_OUT + o] : 0.f;
    bsplit(v, g_Qh[idx], g_Ql[idx]);
}
__global__ void ksplit(const float* __restrict__ kw) {
    int idx = blockIdx.x * 256 + threadIdx.x;
    if (idx >= MP * HD) return;
    int i = idx / HD;
    float v = (i < N_IN) ? kw[idx] : 0.f;
    bsplit(v, g_Kh[idx], g_Kl[idx]);
}

// -------- GEMM1: scoreT[o,i] = (1/16) * sum_h Q[o,h] * K[i,h]  (3xBF16 mma) --------
// BM=BN=128, BK=32, 256 thr, warp grid 2(M)x4(N): warp tile 64x32
__global__ __launch_bounds__(256) void gemm1() {
    __shared__ __nv_bfloat16 Ah[128 * SKEW], Al[128 * SKEW];
    __shared__ __nv_bfloat16 Bh[128 * SKEW], Bl[128 * SKEW];
    const int tid = threadIdx.x, lane = tid & 31, wid = tid >> 5;
    const int wm = (wid >> 2) * 64, wn = (wid & 3) * 32;
    const size_t obase = (size_t)blockIdx.y * 128, ibase = (size_t)blockIdx.x * 128;

    float acc[4][4][4] = {};

    const int a_row = lane & 15;
    const int a_col = (lane >> 4) * 8;
    const int b_row = ((lane >> 4) & 1) * 8 + (lane & 7);
    const int b_col = ((lane >> 3) & 1) * 8;

    for (int k0 = 0; k0 < HD; k0 += 32) {
        #pragma unroll
        for (int s = 0; s < 2; s++) {
            int v = tid + s * 256;          // 0..511
            int r = v >> 2, c = (v & 3) * 8;
            *(uint4*)&Ah[r * SKEW + c] = *(const uint4*)&g_Qh[(obase + r) * HD + k0 + c];
            *(uint4*)&Al[r * SKEW + c] = *(const uint4*)&g_Ql[(obase + r) * HD + k0 + c];
            *(uint4*)&Bh[r * SKEW + c] = *(const uint4*)&g_Kh[(ibase + r) * HD + k0 + c];
            *(uint4*)&Bl[r * SKEW + c] = *(const uint4*)&g_Kl[(ibase + r) * HD + k0 + c];
        }
        __syncthreads();

        #pragma unroll
        for (int ks = 0; ks < 32; ks += 16) {
            uint32_t fah[4][4], fal[4][4], fbh[4][2], fbl[4][2];
            #pragma unroll
            for (int mt = 0; mt < 4; mt++) {
                ldsm4(fah[mt], s2u(&Ah[(wm + mt * 16 + a_row) * SKEW + ks + a_col]));
                ldsm4(fal[mt], s2u(&Al[(wm + mt * 16 + a_row) * SKEW + ks + a_col]));
            }
            #pragma unroll
            for (int nt2 = 0; nt2 < 2; nt2++) {
                uint32_t t[4];
                ldsm4(t, s2u(&Bh[(wn + nt2 * 16 + b_row) * SKEW + ks + b_col]));
                fbh[nt2 * 2][0] = t[0]; fbh[nt2 * 2][1] = t[1];
                fbh[nt2 * 2 + 1][0] = t[2]; fbh[nt2 * 2 + 1][1] = t[3];
                ldsm4(t, s2u(&Bl[(wn + nt2 * 16 + b_row) * SKEW + ks + b_col]));
                fbl[nt2 * 2][0] = t[0]; fbl[nt2 * 2][1] = t[1];
                fbl[nt2 * 2 + 1][0] = t[2]; fbl[nt2 * 2 + 1][1] = t[3];
            }
            #pragma unroll
            for (int mt = 0; mt < 4; mt++)
                #pragma unroll
                for (int nt = 0; nt < 4; nt++) {
                    mma16816(acc[mt][nt], fah[mt], fbh[nt]);
                    mma16816(acc[mt][nt], fah[mt], fbl[nt]);
                    mma16816(acc[mt][nt], fal[mt], fbh[nt]);
                }
        }
        __syncthreads();
    }

    // epilogue: scale by 1/16, split to bf16 hi/lo pairs
    const int g = lane >> 2, t4 = lane & 3;
    #pragma unroll
    for (int mt = 0; mt < 4; mt++)
        #pragma unroll
        for (int nt = 0; nt < 4; nt++) {
            float c0 = acc[mt][nt][0] * 0.0625f, c1 = acc[mt][nt][1] * 0.0625f;
            float c2 = acc[mt][nt][2] * 0.0625f, c3 = acc[mt][nt][3] * 0.0625f;
            size_t o0 = obase + wm + mt * 16 + g;
            size_t i0 = ibase + wn + nt * 8 + 2 * t4;
            __nv_bfloat16 h0, l0, h1, l1v;
            bsplit(c0, h0, l0); bsplit(c1, h1, l1v);
            __nv_bfloat162 ph; ph.x = h0; ph.y = h1;
            __nv_bfloat162 pl; pl.x = l0; pl.y = l1v;
            *(__nv_bfloat162*)&g_Sh[o0 * MP + i0] = ph;
            *(__nv_bfloat162*)&g_Sl[o0 * MP + i0] = pl;
            bsplit(c2, h0, l0); bsplit(c3, h1, l1v);
            ph.x = h0; ph.y = h1; pl.x = l0; pl.y = l1v;
            *(__nv_bfloat162*)&g_Sh[(o0 + 8) * MP + i0] = ph;
            *(__nv_bfloat162*)&g_Sl[(o0 + 8) * MP + i0] = pl;
        }
}

// -------- L1 column sums over o (two-stage, deterministic) --------
__global__ void l1_partial() {
    int i = blockIdx.x * 256 + threadIdx.x;
    int o0 = blockIdx.y * 128;
    float s = 0.f;
    for (int o = o0; o < o0 + 128; o++) {
        size_t off = (size_t)o * MP + i;
        s += fabsf(__bfloat162float(g_Sh[off]) + __bfloat162float(g_Sl[off]));
    }
    g_l1p[blockIdx.y * MP + i] = s;
}
__global__ void l1_final() {
    int i = blockIdx.x * 256 + threadIdx.x;
    float s = 0.f;
    #pragma unroll
    for (int y = 0; y < 40; y++) s += g_l1p[y * MP + i];
    g_rl1[i] = 1.f / fmaxf(s, 1e-12f);
}

// -------- V build: Vt[n][i] = (x @ vw^T)[i,n] * rl1[i], split hi/lo --------
__global__ void vsplit(const float* __restrict__ x, const float* __restrict__ vw) {
    int idx = blockIdx.x * 256 + threadIdx.x;
    if (idx >= NV * MP) return;
    int n = idx / MP, i = idx % MP;
    float v = 0.f;
    if (i < N_IN) {
        int b = n / 3, d = n % 3;
        const float* xp = x + ((size_t)b * N_IN + i) * 3;
        v = (xp[0] * vw[d * 3 + 0] + xp[1] * vw[d * 3 + 1] + xp[2] * vw[d * 3 + 2]) * g_rl1[i];
    }
    bsplit(v, g_Vh[idx], g_Vl[idx]);
}

// -------- GEMM2: out[o,n] = sum_i score[o,i] * Vt[n,i]  (3xBF16 mma) --------
// BM=64, BN=96, BK=32, 256 thr, warp grid 4(M)x2(N): warp tile 16x48
__global__ __launch_bounds__(256) void gemm2(float* __restrict__ out) {
    __shared__ __nv_bfloat16 Ah[64 * SKEW], Al[64 * SKEW];
    __shared__ __nv_bfloat16 Bh[96 * SKEW], Bl[96 * SKEW];
    const int tid = threadIdx.x, lane = tid & 31, wid = tid >> 5;
    const int wm = (wid & 3) * 16, wn = (wid >> 2) * 48;
    const size_t obase = (size_t)blockIdx.y * 64;
    const size_t nbase = (size_t)blockIdx.x * 96;

    float acc[6][4] = {};

    const int a_row = lane & 15;
    const int a_col = (lane >> 4) * 8;
    const int b_row = ((lane >> 4) & 1) * 8 + (lane & 7);
    const int b_col = ((lane >> 3) & 1) * 8;

    for (int k0 = 0; k0 < MP; k0 += 32) {
        {
            int v = tid;                    // A: 64 rows x 4 vec = 256
            int r = v >> 2, c = (v & 3) * 8;
            *(uint4*)&Ah[r * SKEW + c] = *(const uint4*)&g_Sh[(obase + r) * MP + k0 + c];
            *(uint4*)&Al[r * SKEW + c] = *(const uint4*)&g_Sl[(obase + r) * MP + k0 + c];
        }
        for (int v = tid; v < 384; v += 256) {   // B: 96 rows x 4 vec
            int r = v >> 2, c = (v & 3) * 8;
            *(uint4*)&Bh[r * SKEW + c] = *(const uint4*)&g_Vh[(nbase + r) * MP + k0 + c];
            *(uint4*)&Bl[r * SKEW + c] = *(const uint4*)&g_Vl[(nbase + r) * MP + k0 + c];
        }
        __syncthreads();

        #pragma unroll
        for (int ks = 0; ks < 32; ks += 16) {
            uint32_t fah[4], fal[4], fbh[6][2], fbl[6][2];
            ldsm4(fah, s2u(&Ah[(wm + a_row) * SKEW + ks + a_col]));
            ldsm4(fal, s2u(&Al[(wm + a_row) * SKEW + ks + a_col]));
            #pragma unroll
            for (int nt2 = 0; nt2 < 3; nt2++) {
                uint32_t t[4];
                ldsm4(t, s2u(&Bh[(wn + nt2 * 16 + b_row) * SKEW + ks + b_col]));
                fbh[nt2 * 2][0] = t[0]; fbh[nt2 * 2][1] = t[1];
                fbh[nt2 * 2 + 1][0] = t[2]; fbh[nt2 * 2 + 1][1] = t[3];
                ldsm4(t, s2u(&Bl[(wn + nt2 * 16 + b_row) * SKEW + ks + b_col]));
                fbl[nt2 * 2][0] = t[0]; fbl[nt2 * 2][1] = t[1];
                fbl[nt2 * 2 + 1][0] = t[2]; fbl[nt2 * 2 + 1][1] = t[3];
            }
            #pragma unroll
            for (int nt = 0; nt < 6; nt++) {
                mma16816(acc[nt], fah, fbh[nt]);
                mma16816(acc[nt], fah, fbl[nt]);
                mma16816(acc[nt], fal, fbh[nt]);
            }
        }
        __syncthreads();
    }

    // epilogue: scatter to out[b, o, d] with n = b*3+d
    const int g = lane >> 2, t4 = lane & 3;
    #pragma unroll
    for (int nt = 0; nt < 6; nt++) {
        size_t o0 = obase + wm + g;
        int n0 = (int)nbase + wn + nt * 8 + 2 * t4;
        #pragma unroll
        for (int half = 0; half < 2; half++) {
            size_t o = o0 + half * 8;
            if (o < N_OUT) {
                float v0 = acc[nt][half * 2 + 0];
                float v1 = acc[nt][half * 2 + 1];
                int b0 = n0 / 3, d0 = n0 % 3;
                int b1 = (n0 + 1) / 3, d1 = (n0 + 1) % 3;
                out[((size_t)b0 * N_OUT + o) * 3 + d0] = v0;
                out[((size_t)b1 * N_OUT + o) * 3 + d1] = v1;
            }
        }
    }
}

// -------- launch --------
extern "C" void kernel_launch(void* const* d_in, const int* in_sizes, int n_in,
                              void* d_out, int out_size) {
    const float* x  = (const float*)d_in[0];   // [64, 5023, 3]
    const float* kw = (const float*)d_in[1];   // [5023, 256]
    const float* qw = (const float*)d_in[2];   // [256, 5023]
    const float* vw = (const float*)d_in[3];   // [3, 3]
    float* out = (float*)d_out;                // [64, 5023, 3]
    (void)in_sizes; (void)n_in; (void)out_size;

    qsplit<<<(MP * HD + 255) / 256, 256>>>(qw);
    ksplit<<<(MP * HD + 255) / 256, 256>>>(kw);

    gemm1<<<dim3(40, 40), 256>>>();

    l1_partial<<<dim3(MP / 256, 40), 256>>>();
    l1_final<<<MP / 256, 256>>>();
    vsplit<<<(NV * MP + 255) / 256, 256>>>(x, vw);

    gemm2<<<dim3(2, 80), 256>>>(out);
}

// round 6
// speedup vs baseline: 4.8560x; 2.9954x over previous
#include <cuda_runtime.h>
#include <cuda_bf16.h>
#include <cstdint>

#define N_IN  5023
#define N_OUT 5023
#define HD    256
#define MP    5120
#define NV    192
#define SKEW  40   // bf16 smem row stride

// -------- scratch --------
__device__ __nv_bfloat16 g_Qb[(size_t)MP * HD];  // [o][h] bf16
__device__ __nv_bfloat16 g_Kb[(size_t)MP * HD];  // [i][h] bf16
__device__ float g_l1p[40 * MP];                 // per-oblock partial |score| col sums
__device__ float g_rl1[MP];                      // (1/16)/max(l1,eps) folded scale
__device__ float g_V2[(size_t)MP * NV];          // [i][n] = (x@vw^T)*rl1
__device__ float g_Wp[40 * HD * NV];             // split-K partials of W
__device__ float g_W[HD * NV];                   // [h][n]

// -------- helpers --------
__device__ __forceinline__ uint32_t s2u(const void* p) {
    return (uint32_t)__cvta_generic_to_shared(p);
}
__device__ __forceinline__ void ldsm4(uint32_t* r, uint32_t a) {
    asm volatile("ldmatrix.sync.aligned.m8n8.x4.shared.b16 {%0,%1,%2,%3}, [%4];"
                 : "=r"(r[0]), "=r"(r[1]), "=r"(r[2]), "=r"(r[3]) : "r"(a));
}
__device__ __forceinline__ void mma16816(float* d, const uint32_t* a, const uint32_t* b) {
    asm volatile("mma.sync.aligned.m16n8k16.row.col.f32.bf16.bf16.f32 "
                 "{%0,%1,%2,%3},{%4,%5,%6,%7},{%8,%9},{%0,%1,%2,%3};"
                 : "+f"(d[0]), "+f"(d[1]), "+f"(d[2]), "+f"(d[3])
                 : "r"(a[0]), "r"(a[1]), "r"(a[2]), "r"(a[3]), "r"(b[0]), "r"(b[1]));
}

// -------- prep: bf16 conversions (Q transposed to [o][h]) --------
__global__ void qconv(const float* __restrict__ qw) {
    int idx = blockIdx.x * 256 + threadIdx.x;
    if (idx >= MP * HD) return;
    int o = idx / HD, h = idx % HD;
    g_Qb[idx] = __float2bfloat16((o < N_OUT) ? qw[(size_t)h * N_OUT + o] : 0.f);
}
__global__ void kconv(const float* __restrict__ kw) {
    int idx = blockIdx.x * 256 + threadIdx.x;
    if (idx >= MP * HD) return;
    int i = idx / HD;
    g_Kb[idx] = __float2bfloat16((i < N_IN) ? kw[idx] : 0.f);
}

// -------- fused GEMM1 + |.| column reduction --------
// raw[o,i] = sum_h Q[o,h]K[i,h];  partial_l1[by][i] = sum_{o in block} |raw|
// BM=BN=128, BK=32, 256 thr, warps 2(M)x4(N), warp tile 64x32
__global__ __launch_bounds__(256) void gemm1_l1() {
    __shared__ __nv_bfloat16 Ah[128 * SKEW];
    __shared__ __nv_bfloat16 Bh[128 * SKEW];
    __shared__ float Cs[2][128];
    const int tid = threadIdx.x, lane = tid & 31, wid = tid >> 5;
    const int wm = (wid >> 2) * 64, wn = (wid & 3) * 32;
    const size_t obase = (size_t)blockIdx.y * 128, ibase = (size_t)blockIdx.x * 128;

    float acc[4][4][4] = {};

    const int a_row = lane & 15;
    const int a_col = (lane >> 4) * 8;
    const int b_row = ((lane >> 4) & 1) * 8 + (lane & 7);
    const int b_col = ((lane >> 3) & 1) * 8;

    for (int k0 = 0; k0 < HD; k0 += 32) {
        #pragma unroll
        for (int s = 0; s < 2; s++) {
            int v = tid + s * 256;
            int r = v >> 2, c = (v & 3) * 8;
            *(uint4*)&Ah[r * SKEW + c] = *(const uint4*)&g_Qb[(obase + r) * HD + k0 + c];
            *(uint4*)&Bh[r * SKEW + c] = *(const uint4*)&g_Kb[(ibase + r) * HD + k0 + c];
        }
        __syncthreads();

        #pragma unroll
        for (int ks = 0; ks < 32; ks += 16) {
            uint32_t fa[4][4], fb[4][2];
            #pragma unroll
            for (int mt = 0; mt < 4; mt++)
                ldsm4(fa[mt], s2u(&Ah[(wm + mt * 16 + a_row) * SKEW + ks + a_col]));
            #pragma unroll
            for (int nt2 = 0; nt2 < 2; nt2++) {
                uint32_t t[4];
                ldsm4(t, s2u(&Bh[(wn + nt2 * 16 + b_row) * SKEW + ks + b_col]));
                fb[nt2 * 2][0] = t[0]; fb[nt2 * 2][1] = t[1];
                fb[nt2 * 2 + 1][0] = t[2]; fb[nt2 * 2 + 1][1] = t[3];
            }
            #pragma unroll
            for (int mt = 0; mt < 4; mt++)
                #pragma unroll
                for (int nt = 0; nt < 4; nt++)
                    mma16816(acc[mt][nt], fa[mt], fb[nt]);
        }
        __syncthreads();
    }

    // column |.| sums: thread covers rows {g,g+8} per mt, cols {2t4, 2t4+1} per nt
    const int t4 = lane & 3;
    float cs[4][2];
    #pragma unroll
    for (int nt = 0; nt < 4; nt++) {
        float s0 = 0.f, s1 = 0.f;
        #pragma unroll
        for (int mt = 0; mt < 4; mt++) {
            s0 += fabsf(acc[mt][nt][0]) + fabsf(acc[mt][nt][2]);
            s1 += fabsf(acc[mt][nt][1]) + fabsf(acc[mt][nt][3]);
        }
        cs[nt][0] = s0; cs[nt][1] = s1;
    }
    // reduce over g (lanes stride 4)
    #pragma unroll
    for (int m = 4; m <= 16; m <<= 1)
        #pragma unroll
        for (int nt = 0; nt < 4; nt++) {
            cs[nt][0] += __shfl_xor_sync(0xffffffff, cs[nt][0], m);
            cs[nt][1] += __shfl_xor_sync(0xffffffff, cs[nt][1], m);
        }
    if (lane < 4) {
        #pragma unroll
        for (int nt = 0; nt < 4; nt++) {
            Cs[wm >> 6][wn + nt * 8 + 2 * t4 + 0] = cs[nt][0];
            Cs[wm >> 6][wn + nt * 8 + 2 * t4 + 1] = cs[nt][1];
        }
    }
    __syncthreads();
    if (tid < 128)
        g_l1p[blockIdx.y * MP + ibase + tid] = Cs[0][tid] + Cs[1][tid];
}

// rl1[i] = (1/16)/max(raw_l1/16, eps)
__global__ void l1_final() {
    int i = blockIdx.x * 256 + threadIdx.x;
    float s = 0.f;
    #pragma unroll
    for (int y = 0; y < 40; y++) s += g_l1p[y * MP + i];
    g_rl1[i] = 0.0625f / fmaxf(s * 0.0625f, 1e-12f);
}

// V2[i][n] = (x@vw^T)[i,n] * rl1[i]
__global__ void vmat(const float* __restrict__ x, const float* __restrict__ vw) {
    int idx = blockIdx.x * 256 + threadIdx.x;
    if (idx >= MP * NV) return;
    int i = idx / NV, n = idx % NV;
    float v = 0.f;
    if (i < N_IN) {
        int b = n / 3, d = n % 3;
        const float* xp = x + ((size_t)b * N_IN + i) * 3;
        v = (xp[0] * vw[d * 3 + 0] + xp[1] * vw[d * 3 + 1] + xp[2] * vw[d * 3 + 2]) * g_rl1[i];
    }
    g_V2[idx] = v;
}

// -------- W partials: Wp[by][h][n] = sum_{i in chunk} kw[i,h] * V2[i,n] --------
// grid (16, 40): 64h x 48n tile, i-chunk 128. fp32.
__global__ __launch_bounds__(256) void wgemm(const float* __restrict__ kw) {
    __shared__ float Ks[128][68];
    __shared__ float Vs[128][52];
    const int tid = threadIdx.x;
    const int ht = (blockIdx.x & 3) * 64;
    const int ntile = (blockIdx.x >> 2) * 48;
    const int i0 = blockIdx.y * 128;

    // load kw chunk [128 x 64], guarded (kw rows are 256 floats -> 16B aligned)
    #pragma unroll
    for (int s = 0; s < 8; s++) {
        int v = tid + s * 256;
        int r = v >> 4, c = (v & 15) * 4;
        int gi = i0 + r;
        float4 val = make_float4(0.f, 0.f, 0.f, 0.f);
        if (gi < N_IN) val = *(const float4*)&kw[(size_t)gi * HD + ht + c];
        *(float4*)&Ks[r][c] = val;
    }
    // load V2 chunk [128 x 48] (padded rows are zero)
    #pragma unroll
    for (int s = 0; s < 6; s++) {
        int v = tid + s * 256;
        int r = v / 12, c = (v % 12) * 4;
        *(float4*)&Vs[r][c] = *(const float4*)&g_V2[(size_t)(i0 + r) * NV + ntile + c];
    }
    __syncthreads();

    const int th = (tid & 15) * 4, tn = (tid >> 4) * 3;
    float acc[4][3] = {};
    for (int kk = 0; kk < 128; kk++) {
        float ra[4], rb[3];
        #pragma unroll
        for (int u = 0; u < 4; u++) ra[u] = Ks[kk][th + u];
        #pragma unroll
        for (int u = 0; u < 3; u++) rb[u] = Vs[kk][tn + u];
        #pragma unroll
        for (int a = 0; a < 4; a++)
            #pragma unroll
            for (int b = 0; b < 3; b++)
                acc[a][b] += ra[a] * rb[b];
    }
    float* dst = &g_Wp[(size_t)blockIdx.y * HD * NV];
    #pragma unroll
    for (int a = 0; a < 4; a++)
        #pragma unroll
        for (int b = 0; b < 3; b++)
            dst[(ht + th + a) * NV + ntile + tn + b] = acc[a][b];
}

__global__ void wreduce() {
    int idx = blockIdx.x * 256 + threadIdx.x;
    if (idx >= HD * NV) return;
    float s = 0.f;
    #pragma unroll
    for (int y = 0; y < 40; y++) s += g_Wp[(size_t)y * HD * NV + idx];
    g_W[idx] = s;
}

// -------- final: out[o,n] = sum_h qw[h][o] * W[h][n] --------
// grid (4, 40): 128o x 48n tile, BK=16. fp32. Scalar qw loads (5023 stride is
// not 16B aligned; float4 would fault).
__global__ __launch_bounds__(256) void gemm3(const float* __restrict__ qw,
                                             float* __restrict__ out) {
    __shared__ float Qs[16][128];
    __shared__ float Ws[16][52];
    const int tid = threadIdx.x;
    const int ob = blockIdx.y * 128;
    const int nb = blockIdx.x * 48;

    const int to = (tid & 31) * 4, tn = (tid >> 5) * 6;
    float acc[4][6] = {};

    for (int h0 = 0; h0 < HD; h0 += 16) {
        // Qs[r][c] = qw[h0+r][ob+c], scalar guarded loads
        #pragma unroll
        for (int s = 0; s < 8; s++) {
            int v = tid + s * 256;          // 0..2047
            int r = v >> 7, c = v & 127;
            int go = ob + c;
            Qs[r][c] = (go < N_OUT) ? qw[(size_t)(h0 + r) * N_OUT + go] : 0.f;
        }
        // Ws[r][c] = g_W[h0+r][nb+c], 16x48 = 768 elems
        for (int v = tid; v < 768; v += 256) {
            int r = v / 48, c = v % 48;
            Ws[r][c] = g_W[(h0 + r) * NV + nb + c];
        }
        __syncthreads();
        #pragma unroll
        for (int kk = 0; kk < 16; kk++) {
            float ra[4], rb[6];
            #pragma unroll
            for (int u = 0; u < 4; u++) ra[u] = Qs[kk][to + u];
            #pragma unroll
            for (int u = 0; u < 6; u++) rb[u] = Ws[kk][tn + u];
            #pragma unroll
            for (int a = 0; a < 4; a++)
                #pragma unroll
                for (int b = 0; b < 6; b++)
                    acc[a][b] += ra[a] * rb[b];
        }
        __syncthreads();
    }

    #pragma unroll
    for (int a = 0; a < 4; a++) {
        int o = ob + to + a;
        if (o >= N_OUT) continue;
        #pragma unroll
        for (int b = 0; b < 6; b++) {
            int n = nb + tn + b;
            out[((size_t)(n / 3) * N_OUT + o) * 3 + (n % 3)] = acc[a][b];
        }
    }
}

// -------- launch --------
extern "C" void kernel_launch(void* const* d_in, const int* in_sizes, int n_in,
                              void* d_out, int out_size) {
    const float* x  = (const float*)d_in[0];   // [64, 5023, 3]
    const float* kw = (const float*)d_in[1];   // [5023, 256]
    const float* qw = (const float*)d_in[2];   // [256, 5023]
    const float* vw = (const float*)d_in[3];   // [3, 3]
    float* out = (float*)d_out;                // [64, 5023, 3]
    (void)in_sizes; (void)n_in; (void)out_size;

    qconv<<<(MP * HD + 255) / 256, 256>>>(qw);
    kconv<<<(MP * HD + 255) / 256, 256>>>(kw);

    gemm1_l1<<<dim3(40, 40), 256>>>();
    l1_final<<<MP / 256, 256>>>();

    vmat<<<(MP * NV + 255) / 256, 256>>>(x, vw);
    wgemm<<<dim3(16, 40), 256>>>(kw);
    wreduce<<<(HD * NV + 255) / 256, 256>>>();

    gemm3<<<dim3(4, 40), 256>>>(qw, out);
}

// round 12
// speedup vs baseline: 4.9555x; 1.0205x over previous
#include <cuda_runtime.h>
#include <cuda_bf16.h>
#include <cstdint>

#define N_IN  5023
#define N_OUT 5023
#define HD    256
#define MP    5120
#define NV    192
#define WSPLIT 10
#define LDA   72            // smem row stride (bf16) inside gemm1 stages; 144B -> ldsm conflict-free

// -------- scratch --------
__device__ __nv_bfloat16 g_Qb[(size_t)MP * HD];  // [o][h] bf16
__device__ __nv_bfloat16 g_Kb[(size_t)MP * HD];  // [i][h] bf16
__device__ float g_l1p[40 * MP];
__device__ float g_rl1[MP];
__device__ float g_V2[(size_t)MP * NV];
__device__ float g_Wp[WSPLIT * HD * NV];
__device__ float g_W[HD * NV];

// -------- helpers --------
__device__ __forceinline__ uint32_t s2u(const void* p) {
    return (uint32_t)__cvta_generic_to_shared(p);
}
__device__ __forceinline__ void ldsm4(uint32_t* r, uint32_t a) {
    asm volatile("ldmatrix.sync.aligned.m8n8.x4.shared.b16 {%0,%1,%2,%3}, [%4];"
                 : "=r"(r[0]), "=r"(r[1]), "=r"(r[2]), "=r"(r[3]) : "r"(a));
}
__device__ __forceinline__ void mma16816(float* d, const uint32_t* a, const uint32_t* b) {
    asm volatile("mma.sync.aligned.m16n8k16.row.col.f32.bf16.bf16.f32 "
                 "{%0,%1,%2,%3},{%4,%5,%6,%7},{%8,%9},{%0,%1,%2,%3};"
                 : "+f"(d[0]), "+f"(d[1]), "+f"(d[2]), "+f"(d[3])
                 : "r"(a[0]), "r"(a[1]), "r"(a[2]), "r"(a[3]), "r"(b[0]), "r"(b[1]));
}
__device__ __forceinline__ void cpasync16(uint32_t dst, const void* src) {
    asm volatile("cp.async.cg.shared.global [%0], [%1], 16;" :: "r"(dst), "l"(src));
}

// -------- prep --------
// tiled transpose: g_Qb[o][h] = bf16(qw[h][o])
__global__ void qconv(const float* __restrict__ qw) {
    __shared__ float t[32][33];
    const int o0 = blockIdx.x * 32, h0 = blockIdx.y * 32;
    const int tx = threadIdx.x & 31, ty = threadIdx.x >> 5;   // 32 x 8
    #pragma unroll
    for (int j = 0; j < 4; j++) {
        int h = h0 + ty + j * 8, o = o0 + tx;
        t[ty + j * 8][tx] = (o < N_OUT) ? qw[(size_t)h * N_OUT + o] : 0.f;
    }
    __syncthreads();
    #pragma unroll
    for (int j = 0; j < 4; j++) {
        int o = o0 + ty + j * 8, h = h0 + tx;
        g_Qb[(size_t)o * HD + h] = __float2bfloat16(t[tx][ty + j * 8]);
    }
}
__global__ void kconv(const float* __restrict__ kw) {
    int idx = blockIdx.x * 256 + threadIdx.x;
    if (idx >= MP * HD) return;
    int i = idx / HD;
    g_Kb[idx] = __float2bfloat16((i < N_IN) ? kw[idx] : 0.f);
}

// -------- fused GEMM1 + |.| column reduction (cp.async, fully K-resident) --------
// BM=BN=128, 4 stages of BK=64; 256 thr, warps 2(M)x4(N), warp tile 64x32.
#define STAGE_BYTES 36864u     // A(128*72*2) + B(128*72*2)
#define OFF_CS      147456u
#define G1_SMEM     148480u

__global__ __launch_bounds__(256) void gemm1_l1() {
    extern __shared__ char smem[];
    const uint32_t sb = s2u(smem);
    const int tid = threadIdx.x, lane = tid & 31, wid = tid >> 5;
    const int wm = (wid >> 2) * 64, wn = (wid & 3) * 32;
    const size_t obase = (size_t)blockIdx.y * 128, ibase = (size_t)blockIdx.x * 128;

    // issue all 4 stages
    #pragma unroll
    for (int s = 0; s < 4; s++) {
        const int k0 = s * 64;
        const uint32_t sa = sb + s * STAGE_BYTES;
        const uint32_t sbB = sa + 18432u;
        #pragma unroll
        for (int j = 0; j < 4; j++) {
            int v = tid + j * 256;
            int r = v >> 3, c8 = (v & 7) * 8;
            cpasync16(sa  + (uint32_t)(r * LDA + c8) * 2, &g_Qb[(obase + r) * HD + k0 + c8]);
            cpasync16(sbB + (uint32_t)(r * LDA + c8) * 2, &g_Kb[(ibase + r) * HD + k0 + c8]);
        }
        asm volatile("cp.async.commit_group;" ::: "memory");
    }

    float acc[4][4][4] = {};
    const int a_row = lane & 15;
    const int a_col = (lane >> 4) * 8;
    const int b_row = ((lane >> 4) & 1) * 8 + (lane & 7);
    const int b_col = ((lane >> 3) & 1) * 8;

#define COMPUTE_STAGE(S)                                                          \
    {                                                                             \
        const uint32_t sa = sb + (S) * STAGE_BYTES;                               \
        const uint32_t sbB = sa + 18432u;                                         \
        _Pragma("unroll")                                                         \
        for (int ks = 0; ks < 64; ks += 16) {                                     \
            uint32_t fa[4][4], fb[4][2];                                          \
            _Pragma("unroll")                                                     \
            for (int mt = 0; mt < 4; mt++)                                        \
                ldsm4(fa[mt], sa + (uint32_t)((wm + mt * 16 + a_row) * LDA + ks + a_col) * 2); \
            _Pragma("unroll")                                                     \
            for (int nt2 = 0; nt2 < 2; nt2++) {                                   \
                uint32_t t[4];                                                    \
                ldsm4(t, sbB + (uint32_t)((wn + nt2 * 16 + b_row) * LDA + ks + b_col) * 2); \
                fb[nt2 * 2][0] = t[0]; fb[nt2 * 2][1] = t[1];                     \
                fb[nt2 * 2 + 1][0] = t[2]; fb[nt2 * 2 + 1][1] = t[3];             \
            }                                                                     \
            _Pragma("unroll")                                                     \
            for (int mt = 0; mt < 4; mt++)                                        \
                _Pragma("unroll")                                                 \
                for (int nt = 0; nt < 4; nt++)                                    \
                    mma16816(acc[mt][nt], fa[mt], fb[nt]);                        \
        }                                                                         \
    }

    asm volatile("cp.async.wait_group 3;" ::: "memory"); __syncthreads(); COMPUTE_STAGE(0);
    asm volatile("cp.async.wait_group 2;" ::: "memory"); __syncthreads(); COMPUTE_STAGE(1);
    asm volatile("cp.async.wait_group 1;" ::: "memory"); __syncthreads(); COMPUTE_STAGE(2);
    asm volatile("cp.async.wait_group 0;" ::: "memory"); __syncthreads(); COMPUTE_STAGE(3);
#undef COMPUTE_STAGE

    // column |.| sums
    float* Cs = (float*)(smem + OFF_CS);     // [2][128]
    const int t4 = lane & 3;
    float cs[4][2];
    #pragma unroll
    for (int nt = 0; nt < 4; nt++) {
        float s0 = 0.f, s1 = 0.f;
        #pragma unroll
        for (int mt = 0; mt < 4; mt++) {
            s0 += fabsf(acc[mt][nt][0]) + fabsf(acc[mt][nt][2]);
            s1 += fabsf(acc[mt][nt][1]) + fabsf(acc[mt][nt][3]);
        }
        cs[nt][0] = s0; cs[nt][1] = s1;
    }
    #pragma unroll
    for (int m = 4; m <= 16; m <<= 1)
        #pragma unroll
        for (int nt = 0; nt < 4; nt++) {
            cs[nt][0] += __shfl_xor_sync(0xffffffff, cs[nt][0], m);
            cs[nt][1] += __shfl_xor_sync(0xffffffff, cs[nt][1], m);
        }
    __syncthreads();   // stages dead; Cs region distinct anyway
    if (lane < 4) {
        #pragma unroll
        for (int nt = 0; nt < 4; nt++) {
            Cs[(wm >> 6) * 128 + wn + nt * 8 + 2 * t4 + 0] = cs[nt][0];
            Cs[(wm >> 6) * 128 + wn + nt * 8 + 2 * t4 + 1] = cs[nt][1];
        }
    }
    __syncthreads();
    if (tid < 128)
        g_l1p[blockIdx.y * MP + ibase + tid] = Cs[tid] + Cs[128 + tid];
}

// rl1[i] = (1/16)/max(raw_l1/16, eps); 4-way split per column
__global__ void l1_final() {
    __shared__ float red[3][64];
    const int tx = threadIdx.x & 63, part = threadIdx.x >> 6;
    const int col = blockIdx.x * 64 + tx;
    float s = 0.f;
    for (int y = part; y < 40; y += 4) s += g_l1p[y * MP + col];
    if (part > 0) red[part - 1][tx] = s;
    __syncthreads();
    if (part == 0) {
        s += red[0][tx] + red[1][tx] + red[2][tx];
        g_rl1[col] = 0.0625f / fmaxf(s * 0.0625f, 1e-12f);
    }
}

// V2[i][n]: one thread per (i, b) computes 3 contiguous outputs
__global__ void vmat(const float* __restrict__ x, const float* __restrict__ vw) {
    int idx = blockIdx.x * 256 + threadIdx.x;
    if (idx >= MP * 64) return;
    int i = idx >> 6, b = idx & 63;
    float o0 = 0.f, o1 = 0.f, o2 = 0.f;
    if (i < N_IN) {
        float r = g_rl1[i];
        const float* xp = x + ((size_t)b * N_IN + i) * 3;
        float x0 = xp[0], x1 = xp[1], x2 = xp[2];
        o0 = (x0 * vw[0] + x1 * vw[1] + x2 * vw[2]) * r;
        o1 = (x0 * vw[3] + x1 * vw[4] + x2 * vw[5]) * r;
        o2 = (x0 * vw[6] + x1 * vw[7] + x2 * vw[8]) * r;
    }
    float* dst = &g_V2[(size_t)i * NV + b * 3];
    dst[0] = o0; dst[1] = o1; dst[2] = o2;
}

// -------- W partials --------
__global__ __launch_bounds__(256) void wgemm(const float* __restrict__ kw) {
    __shared__ float Ks[128][68];
    __shared__ float Vs[128][52];
    const int tid = threadIdx.x;
    const int ht = (blockIdx.x & 3) * 64;
    const int ntile = (blockIdx.x >> 2) * 48;
    const int i00 = blockIdx.y * 512;

    const int th = (tid & 15) * 4, tn = (tid >> 4) * 3;
    float acc[4][3] = {};

    for (int ch = 0; ch < 4; ch++) {
        const int i0 = i00 + ch * 128;
        #pragma unroll
        for (int s = 0; s < 8; s++) {
            int v = tid + s * 256;
            int r = v >> 4, c = (v & 15) * 4;
            int gi = i0 + r;
            float4 val = make_float4(0.f, 0.f, 0.f, 0.f);
            if (gi < N_IN) val = *(const float4*)&kw[(size_t)gi * HD + ht + c];
            *(float4*)&Ks[r][c] = val;
        }
        #pragma unroll
        for (int s = 0; s < 6; s++) {
            int v = tid + s * 256;
            int r = v / 12, c = (v % 12) * 4;
            *(float4*)&Vs[r][c] = *(const float4*)&g_V2[(size_t)(i0 + r) * NV + ntile + c];
        }
        __syncthreads();
        for (int kk = 0; kk < 128; kk++) {
            float ra[4], rb[3];
            #pragma unroll
            for (int u = 0; u < 4; u++) ra[u] = Ks[kk][th + u];
            #pragma unroll
            for (int u = 0; u < 3; u++) rb[u] = Vs[kk][tn + u];
            #pragma unroll
            for (int a = 0; a < 4; a++)
                #pragma unroll
                for (int b = 0; b < 3; b++)
                    acc[a][b] += ra[a] * rb[b];
        }
        __syncthreads();
    }
    float* dst = &g_Wp[(size_t)blockIdx.y * HD * NV];
    #pragma unroll
    for (int a = 0; a < 4; a++)
        #pragma unroll
        for (int b = 0; b < 3; b++)
            dst[(ht + th + a) * NV + ntile + tn + b] = acc[a][b];
}

__global__ void wreduce() {
    int idx = blockIdx.x * 256 + threadIdx.x;
    if (idx >= HD * NV) return;
    float s = 0.f;
    #pragma unroll
    for (int y = 0; y < WSPLIT; y++) s += g_Wp[(size_t)y * HD * NV + idx];
    g_W[idx] = s;
}

// -------- final: out[o,n] = sum_h qw[h][o] * W[h][n] --------
__global__ __launch_bounds__(256) void gemm3(const float* __restrict__ qw,
                                             float* __restrict__ out) {
    __shared__ float Qs[16][128];
    __shared__ float Ws[16][52];
    const int tid = threadIdx.x;
    const int ob = blockIdx.y * 128;
    const int nb = blockIdx.x * 48;

    const int to = (tid & 31) * 4, tn = (tid >> 5) * 6;
    float acc[4][6] = {};

    for (int h0 = 0; h0 < HD; h0 += 16) {
        #pragma unroll
        for (int s = 0; s < 8; s++) {
            int v = tid + s * 256;
            int r = v >> 7, c = v & 127;
            int go = ob + c;
            Qs[r][c] = (go < N_OUT) ? qw[(size_t)(h0 + r) * N_OUT + go] : 0.f;
        }
        for (int v = tid; v < 768; v += 256) {
            int r = v / 48, c = v % 48;
            Ws[r][c] = g_W[(h0 + r) * NV + nb + c];
        }
        __syncthreads();
        #pragma unroll
        for (int kk = 0; kk < 16; kk++) {
            float ra[4], rb[6];
            #pragma unroll
            for (int u = 0; u < 4; u++) ra[u] = Qs[kk][to + u];
            #pragma unroll
            for (int u = 0; u < 6; u++) rb[u] = Ws[kk][tn + u];
            #pragma unroll
            for (int a = 0; a < 4; a++)
                #pragma unroll
                for (int b = 0; b < 6; b++)
                    acc[a][b] += ra[a] * rb[b];
        }
        __syncthreads();
    }

    #pragma unroll
    for (int a = 0; a < 4; a++) {
        int o = ob + to + a;
        if (o >= N_OUT) continue;
        #pragma unroll
        for (int b = 0; b < 6; b++) {
            int n = nb + tn + b;
            out[((size_t)(n / 3) * N_OUT + o) * 3 + (n % 3)] = acc[a][b];
        }
    }
}

// -------- launch --------
extern "C" void kernel_launch(void* const* d_in, const int* in_sizes, int n_in,
                              void* d_out, int out_size) {
    const float* x  = (const float*)d_in[0];
    const float* kw = (const float*)d_in[1];
    const float* qw = (const float*)d_in[2];
    const float* vw = (const float*)d_in[3];
    float* out = (float*)d_out;
    (void)in_sizes; (void)n_in; (void)out_size;

    cudaFuncSetAttribute(gemm1_l1, cudaFuncAttributeMaxDynamicSharedMemorySize, G1_SMEM);

    qconv<<<dim3(160, 8), 256>>>(qw);
    kconv<<<(MP * HD + 255) / 256, 256>>>(kw);

    gemm1_l1<<<dim3(40, 40), 256, G1_SMEM>>>();
    l1_final<<<80, 256>>>();

    vmat<<<(MP * 64 + 255) / 256, 256>>>(x, vw);
    wgemm<<<dim3(16, WSPLIT), 256>>>(kw);
    wreduce<<<(HD * NV + 255) / 256, 256>>>();

    gemm3<<<dim3(4, 40), 256>>>(qw, out);
}